// round 1
// baseline (speedup 1.0000x reference)
#include <cuda_runtime.h>
#include <cstdint>

// ---------------------------------------------------------------------------
// VQ-VAE EMA quantizer.
// Inputs : x[16384,64] f32, codebook[8192,64] f32, ema_count[8192] f32,
//          ema_weight[8192,64] f32
// Outputs (concatenated f32, 136,323,072 elems):
//   discrete [16384,8192] | quantized [16384,64] | new_count [8192]
//   | new_weight [8192,64] | new_codebook [8192,64]
// ---------------------------------------------------------------------------

#define N_TOK   16384
#define K_CODES 8192
#define DIM     64

#define OFF_QUANT   134217728   // 16384*8192
#define OFF_COUNT   135266304   // + 16384*64
#define OFF_WEIGHT  135274496   // + 8192
#define OFF_CB      135798784   // + 8192*64

// Scratch (no allocations allowed -> __device__ globals)
__device__ int   g_idx[N_TOK];
__device__ float g_halfnorm[K_CODES];
__device__ float g_hist[K_CODES];
__device__ float g_accum[K_CODES * DIM];

// Packed fp32x2 FMA (Blackwell): doubles fp32 MAC throughput vs scalar FFMA.
#define FMA_F32X2(d_, a_, b_, c_) \
    asm("fma.rn.f32x2 %0, %1, %2, %3;" : "=l"(d_) : "l"(a_), "l"(b_), "l"(c_))

// ---------------------------------------------------------------------------
// Kernel 1: half code norms + zero scratch (hist, accum)
// ---------------------------------------------------------------------------
__global__ void prep_kernel(const float* __restrict__ cb) {
    int k = blockIdx.x * 256 + threadIdx.x;   // 8192 threads
    const float4* row = (const float4*)(cb + k * DIM);
    float s = 0.f;
#pragma unroll
    for (int i = 0; i < 16; i++) {
        float4 v = row[i];
        s += v.x * v.x + v.y * v.y + v.z * v.z + v.w * v.w;
    }
    g_halfnorm[k] = 0.5f * s;
    g_hist[k] = 0.f;
    float4 z = make_float4(0.f, 0.f, 0.f, 0.f);
    float4* acc = (float4*)(g_accum + k * DIM);
#pragma unroll
    for (int i = 0; i < 16; i++) acc[i] = z;
}

// ---------------------------------------------------------------------------
// Kernel 2: argmax_k (x . c_k - 0.5*||c_k||^2)  ==  argmin_k distance
//
// Block: 256 threads = 8 warps. Tile: 32 tokens x full K sweep.
// Per chunk: 256 codes staged in smem (padded stride 17 float4s -> conflict
// free for the lane-distinct code reads; x reads are warp-uniform broadcast).
// Per thread: 4 tokens x 8 codes, accumulators are f32x2 pairs over d.
// ---------------------------------------------------------------------------
#define TTOK 32
#define CCH  256
#define ARG_SMEM_BYTES ((TTOK * 17 + CCH * 17) * 16 + CCH * 4)   // 79360 B

__global__ __launch_bounds__(256, 2)
void argmax_kernel(const float* __restrict__ x, const float* __restrict__ cb) {
    extern __shared__ float4 sm4[];
    float4* xs = sm4;                         // [TTOK][17]
    float4* cs = sm4 + TTOK * 17;             // [CCH][17]
    float*  cn = (float*)(sm4 + TTOK * 17 + CCH * 17);   // [CCH]

    const int tid  = threadIdx.x;
    const int warp = tid >> 5;
    const int lane = tid & 31;
    const int t0   = blockIdx.x * TTOK;

    // Stage x tile: 32 rows x 16 float4 (coalesced)
#pragma unroll
    for (int it = 0; it < 2; it++) {
        int q  = it * 256 + tid;
        int r  = q >> 4, d4 = q & 15;
        xs[r * 17 + d4] = ((const float4*)x)[(t0 + r) * 16 + d4];
    }

    float best[4];
    int   bidx[4];
#pragma unroll
    for (int a = 0; a < 4; a++) { best[a] = -3.0e38f; bidx[a] = 0; }

    for (int base = 0; base < K_CODES; base += CCH) {
        __syncthreads();   // protect cs/cn from previous iteration's readers
#pragma unroll
        for (int it = 0; it < 16; it++) {      // 256 rows x 16 float4
            int q  = it * 256 + tid;
            int r  = q >> 4, d4 = q & 15;
            cs[r * 17 + d4] = ((const float4*)cb)[(base + r) * 16 + d4];
        }
        cn[tid] = g_halfnorm[base + tid];
        __syncthreads();

        unsigned long long acc[4][8];
#pragma unroll
        for (int a = 0; a < 4; a++)
#pragma unroll
            for (int b = 0; b < 8; b++) acc[a][b] = 0ULL;

#pragma unroll
        for (int d4 = 0; d4 < 16; d4++) {
            ulonglong2 xv[4];
#pragma unroll
            for (int a = 0; a < 4; a++)
                xv[a] = *(const ulonglong2*)&xs[(warp * 4 + a) * 17 + d4];
#pragma unroll
            for (int b = 0; b < 8; b++) {
                ulonglong2 cv = *(const ulonglong2*)&cs[(lane + 32 * b) * 17 + d4];
#pragma unroll
                for (int a = 0; a < 4; a++) {
                    FMA_F32X2(acc[a][b], xv[a].x, cv.x, acc[a][b]);
                    FMA_F32X2(acc[a][b], xv[a].y, cv.y, acc[a][b]);
                }
            }
        }

        // Score + running best (codes ascend within a thread -> '>' keeps
        // the earliest (lowest) index among exact ties, matching argmin)
#pragma unroll
        for (int b = 0; b < 8; b++) {
            int   c = lane + 32 * b;
            float h = cn[c];
#pragma unroll
            for (int a = 0; a < 4; a++) {
                unsigned long long v = acc[a][b];
                float lo = __uint_as_float((unsigned)(v & 0xffffffffu));
                float hi = __uint_as_float((unsigned)(v >> 32));
                float s  = (lo + hi) - h;
                if (s > best[a]) { best[a] = s; bidx[a] = base + c; }
            }
        }
    }

    // Reduce across the 32 lanes (max score, tie -> min index)
#pragma unroll
    for (int a = 0; a < 4; a++) {
        float v  = best[a];
        int   ix = bidx[a];
#pragma unroll
        for (int off = 16; off > 0; off >>= 1) {
            float ov = __shfl_down_sync(0xffffffffu, v, off);
            int   oi = __shfl_down_sync(0xffffffffu, ix, off);
            if (ov > v || (ov == v && oi < ix)) { v = ov; ix = oi; }
        }
        if (lane == 0) g_idx[t0 + warp * 4 + a] = ix;
    }
}

// ---------------------------------------------------------------------------
// Kernel 3: one-hot fill (537 MB, HBM-write bound, STG.128)
// ---------------------------------------------------------------------------
__global__ void discrete_kernel(float* __restrict__ out) {
    unsigned g  = blockIdx.x * 256u + threadIdx.x;   // float4 index, 33,554,432 total
    int n   = (int)(g >> 11);                        // 2048 float4 per row
    int c4  = (int)(g & 2047u);
    int idx = g_idx[n];
    float4 v = make_float4(0.f, 0.f, 0.f, 0.f);
    if ((idx >> 2) == c4) ((float*)&v)[idx & 3] = 1.0f;
    ((float4*)out)[g] = v;
}

// ---------------------------------------------------------------------------
// Kernel 4: quantized = codebook[idx[n]]
// ---------------------------------------------------------------------------
__global__ void quant_kernel(const float* __restrict__ cb, float* __restrict__ out) {
    int g  = blockIdx.x * 256 + threadIdx.x;   // 262144 float4
    int n  = g >> 4, d4 = g & 15;
    int idx = g_idx[n];
    ((float4*)out)[g] = ((const float4*)cb)[idx * 16 + d4];
}

// ---------------------------------------------------------------------------
// Kernel 5: histogram + per-dim scatter-add of x into accum
// ---------------------------------------------------------------------------
__global__ void scatter_kernel(const float* __restrict__ x) {
    int g = blockIdx.x * 256 + threadIdx.x;    // 1,048,576 = N*D
    int n = g >> 6, d = g & 63;
    int idx = g_idx[n];
    atomicAdd(&g_accum[idx * DIM + d], x[g]);
    if (d == 0) atomicAdd(&g_hist[idx], 1.0f);
}

// ---------------------------------------------------------------------------
// Kernel 6: EMA update + normalization -> new_count, new_weight, new_codebook
// ---------------------------------------------------------------------------
__global__ void final_kernel(const float* __restrict__ ema_count,
                             const float* __restrict__ ema_weight,
                             float* __restrict__ out_count,
                             float* __restrict__ out_weight,
                             float* __restrict__ out_cb) {
    int g = blockIdx.x * 256 + threadIdx.x;    // 524288 = K*D
    int k = g >> 6, d = g & 63;
    const float DECAY = 0.99f, OMD = 1.0f - 0.99f, EPS = 1e-5f;
    float nc = ema_count[k] * DECAY + g_hist[k] * OMD;
    nc = (nc + EPS) / (32.0f + (float)K_CODES * EPS) * 32.0f;
    float nw = ema_weight[g] * DECAY + g_accum[g] * OMD;
    out_weight[g] = nw;
    out_cb[g]     = nw / nc;
    if (d == 0) out_count[k] = nc;
}

// ---------------------------------------------------------------------------
extern "C" void kernel_launch(void* const* d_in, const int* in_sizes, int n_in,
                              void* d_out, int out_size) {
    const float* x          = (const float*)d_in[0];
    const float* cb         = (const float*)d_in[1];
    const float* ema_count  = (const float*)d_in[2];
    const float* ema_weight = (const float*)d_in[3];
    float* out = (float*)d_out;

    // >48KB dynamic smem opt-in (idempotent, not a stream op -> capture-safe)
    cudaFuncSetAttribute(argmax_kernel,
                         cudaFuncAttributeMaxDynamicSharedMemorySize,
                         ARG_SMEM_BYTES);

    prep_kernel   <<<32,     256>>>(cb);
    argmax_kernel <<<N_TOK / TTOK, 256, ARG_SMEM_BYTES>>>(x, cb);
    discrete_kernel<<<131072, 256>>>(out);
    quant_kernel  <<<1024,   256>>>(cb, out + OFF_QUANT);
    scatter_kernel<<<4096,   256>>>(x);
    final_kernel  <<<2048,   256>>>(ema_count, ema_weight,
                                    out + OFF_COUNT, out + OFF_WEIGHT,
                                    out + OFF_CB);
}

// round 6
// speedup vs baseline: 1.5589x; 1.5589x over previous
#include <cuda_runtime.h>
#include <cuda_fp16.h>
#include <cstdint>

// ---------------------------------------------------------------------------
// VQ-VAE EMA quantizer on GB300 (sm_103 baseline PTX: mma.sync/ldmatrix/cp.async;
// tcgen05 is unavailable because the harness targets compute_103 without 'a').
// ---------------------------------------------------------------------------

#define N_TOK   16384
#define K_CODES 8192
#define DIM     64

#define OFF_QUANT   134217728
#define OFF_COUNT   135266304
#define OFF_WEIGHT  135274496
#define OFF_CB      135798784

// ------------------------- device scratch ----------------------------------
__device__ int     g_idx[N_TOK];
__device__ float   g_halfnorm[K_CODES];
__device__ float   g_hist[K_CODES];
__device__ float   g_accum[K_CODES * DIM];
__device__ int     g_nflag;
__device__ int     g_flist[8192];
// fp16 split operands, rows padded to 256 halfs (512 B):
// X2 row: [x1(64) | x1(64) | x2(64) | 1,1 | zeros]
// C2 row: [c1(64) | c2(64) | c1(64) | -h1,-h2 | zeros]
__device__ __half2 g_X2[N_TOK * 128];
__device__ __half2 g_C2[K_CODES * 128];

// ------------------------- PTX helpers -------------------------------------
__device__ __forceinline__ uint32_t smem_u32(const void* p) {
    uint32_t a;
    asm("{ .reg .u64 t; cvta.to.shared.u64 t, %1; cvt.u32.u64 %0, t; }"
        : "=r"(a) : "l"(p));
    return a;
}
#define CP_ASYNC16(s, g) \
    asm volatile("cp.async.cg.shared.global [%0], [%1], 16;" :: "r"(s), "l"(g))
#define CP_COMMIT() asm volatile("cp.async.commit_group;" ::: "memory")
#define CP_WAIT1()  asm volatile("cp.async.wait_group 1;" ::: "memory")
#define CP_WAIT0()  asm volatile("cp.async.wait_group 0;" ::: "memory")

#define LDSM_X4(r0, r1, r2, r3, addr) \
    asm volatile("ldmatrix.sync.aligned.m8n8.x4.shared.b16 {%0,%1,%2,%3}, [%4];" \
        : "=r"(r0), "=r"(r1), "=r"(r2), "=r"(r3) : "r"(addr))

#define HMMA(c, a, b) \
    asm volatile("mma.sync.aligned.m16n8k16.row.col.f32.f16.f16.f32 " \
        "{%0,%1,%2,%3}, {%4,%5,%6,%7}, {%8,%9}, {%0,%1,%2,%3};" \
        : "+f"((c)[0]), "+f"((c)[1]), "+f"((c)[2]), "+f"((c)[3]) \
        : "r"((a)[0]), "r"((a)[1]), "r"((a)[2]), "r"((a)[3]), \
          "r"((b)[0]), "r"((b)[1]))

// ---------------------------------------------------------------------------
// Kernel 1: half code norms + zero scratch
// ---------------------------------------------------------------------------
__global__ void prep_kernel(const float* __restrict__ cb) {
    int k = blockIdx.x * 256 + threadIdx.x;
    if (blockIdx.x == 0 && threadIdx.x == 0) g_nflag = 0;
    const float4* row = (const float4*)(cb + k * DIM);
    float s = 0.f;
#pragma unroll
    for (int i = 0; i < 16; i++) {
        float4 v = row[i];
        s += v.x * v.x + v.y * v.y + v.z * v.z + v.w * v.w;
    }
    g_halfnorm[k] = 0.5f * s;
    g_hist[k] = 0.f;
    float4 z = make_float4(0.f, 0.f, 0.f, 0.f);
    float4* acc = (float4*)(g_accum + k * DIM);
#pragma unroll
    for (int i = 0; i < 16; i++) acc[i] = z;
}

// ---------------------------------------------------------------------------
// Kernels 2a/2b: build fp16 split operands (K-concatenated, K=208 used)
// ---------------------------------------------------------------------------
__global__ void conv_x_kernel(const float* __restrict__ x) {
    int g = blockIdx.x * 256 + threadIdx.x;       // N_TOK*128
    int r = g >> 7, c2 = g & 127;
    const float* xr = x + r * DIM;
    __half2 v = __float2half2_rn(0.f);
    if (c2 < 32) {
        v = __floats2half2_rn(xr[2 * c2], xr[2 * c2 + 1]);
    } else if (c2 < 64) {
        int d = 2 * (c2 - 32);
        v = __floats2half2_rn(xr[d], xr[d + 1]);
    } else if (c2 < 96) {
        int d = 2 * (c2 - 64);
        float a = xr[d], b = xr[d + 1];
        float ra = a - __half2float(__float2half_rn(a));
        float rb = b - __half2float(__float2half_rn(b));
        v = __floats2half2_rn(ra, rb);
    } else if (c2 == 96) {
        v = __floats2half2_rn(1.f, 1.f);
    }
    g_X2[g] = v;
}

__global__ void conv_c_kernel(const float* __restrict__ cb) {
    int g = blockIdx.x * 256 + threadIdx.x;       // K_CODES*128
    int r = g >> 7, c2 = g & 127;
    const float* cr = cb + r * DIM;
    __half2 v = __float2half2_rn(0.f);
    if (c2 < 32) {
        v = __floats2half2_rn(cr[2 * c2], cr[2 * c2 + 1]);
    } else if (c2 < 64) {
        int d = 2 * (c2 - 32);
        float a = cr[d], b = cr[d + 1];
        float ra = a - __half2float(__float2half_rn(a));
        float rb = b - __half2float(__float2half_rn(b));
        v = __floats2half2_rn(ra, rb);
    } else if (c2 < 96) {
        int d = 2 * (c2 - 64);
        v = __floats2half2_rn(cr[d], cr[d + 1]);
    } else if (c2 == 96) {
        float h = g_halfnorm[r];
        float h1 = __half2float(__float2half_rn(h));
        float h2 = h - h1;
        v = __floats2half2_rn(-h1, -h2);
    }
    g_C2[g] = v;
}

// ---------------------------------------------------------------------------
// Kernel 3: HMMA fused GEMM + top-2 argmax.
// CTA: 256 threads = 8 warps (4 m-warps x 2 n-warps), 128 tokens.
// A fragments register-resident (13 ksteps). B = 128-code chunks,
// cp.async double-buffered in smem, 432-byte row stride (conflict-free).
// ---------------------------------------------------------------------------
#define KSTEPS   13
#define CHUNK_B  55296                 // 128 rows * 432 B
#define RED_OFF  (2 * CHUNK_B)
#define SM_TOTAL (RED_OFF + 128 * 12 + 64)
#define EPS_MARGIN 5e-4f

__device__ __forceinline__ void load_chunk(uint32_t bufsm, int chunk, int tid) {
    const char* base = (const char*)g_C2 + (size_t)chunk * 128 * 512;
#pragma unroll
    for (int j = 0; j < 13; j++) {
        int seg = tid + j * 256;          // 0..3327
        int row = seg / 26, s = seg - row * 26;
        CP_ASYNC16(bufsm + row * 432 + s * 16, base + row * 512 + s * 16);
    }
}

__global__ __launch_bounds__(256, 1)
void mma_argmax_kernel() {
    extern __shared__ char smem[];
    const uint32_t sb = smem_u32(smem);
    const int tid  = threadIdx.x;
    const int wid  = tid >> 5;
    const int lane = tid & 31;
    const int wm   = wid >> 1;            // 0..3
    const int wn   = wid & 1;             // 0..1
    const int t0   = blockIdx.x * 128;

    // Prologue: start streaming chunks 0 and 1
    load_chunk(sb, 0, tid);            CP_COMMIT();
    load_chunk(sb + CHUNK_B, 1, tid);  CP_COMMIT();

    // A fragments (m16k16 row-major), register resident: 2 mtiles x 13 ksteps
    uint32_t a[2][KSTEPS][4];
    {
        const char* xb = (const char*)g_X2;
#pragma unroll
        for (int m = 0; m < 2; m++) {
            size_t r0 = ((size_t)(t0 + wm * 32 + m * 16 + (lane >> 2))) * 512
                      + (size_t)(lane & 3) * 4;
#pragma unroll
            for (int k = 0; k < KSTEPS; k++) {
                a[m][k][0] = *(const uint32_t*)(xb + r0 + k * 32);
                a[m][k][1] = *(const uint32_t*)(xb + r0 + 4096 + k * 32);
                a[m][k][2] = *(const uint32_t*)(xb + r0 + k * 32 + 16);
                a[m][k][3] = *(const uint32_t*)(xb + r0 + 4096 + k * 32 + 16);
            }
        }
    }

    // Top-2 state: 4 token-slots per thread (2 mtiles x 2 row-halves)
    float best[4], sec[4];
    int   bidx[4];
#pragma unroll
    for (int s = 0; s < 4; s++) { best[s] = -3.4e38f; sec[s] = -3.4e38f; bidx[s] = 0; }

    for (int i = 0; i < 64; i++) {
        if (i == 63) CP_WAIT0(); else CP_WAIT1();
        __syncthreads();
        const uint32_t bufb = sb + (i & 1) * CHUNK_B;

#pragma unroll
        for (int h = 0; h < 2; h++) {       // n-halves of the warp's 64 codes
            float acc[2][4][4];
#pragma unroll
            for (int m = 0; m < 2; m++)
#pragma unroll
                for (int n = 0; n < 4; n++)
#pragma unroll
                    for (int q = 0; q < 4; q++) acc[m][n][q] = 0.f;

            const int n0 = wn * 64 + h * 32;
#pragma unroll
            for (int k = 0; k < KSTEPS; k++) {
                uint32_t b[4][2];
#pragma unroll
                for (int p = 0; p < 2; p++) {
                    int row = n0 + p * 16 + ((lane >> 4) & 1) * 8 + (lane & 7);
                    uint32_t ad = bufb + row * 432 + k * 32 + ((lane >> 3) & 1) * 16;
                    LDSM_X4(b[2 * p][0], b[2 * p][1], b[2 * p + 1][0], b[2 * p + 1][1], ad);
                }
#pragma unroll
                for (int m = 0; m < 2; m++)
#pragma unroll
                    for (int n = 0; n < 4; n++)
                        HMMA(acc[m][n], a[m][k], b[n]);
            }

            // Top-2 update (scan order ascending in code index per thread)
            const int cb0 = i * 128 + n0 + 2 * (lane & 3);
#pragma unroll
            for (int m = 0; m < 2; m++)
#pragma unroll
                for (int rh = 0; rh < 2; rh++) {
                    const int s = m * 2 + rh;
#pragma unroll
                    for (int n = 0; n < 4; n++)
#pragma unroll
                        for (int c = 0; c < 2; c++) {
                            float v  = acc[m][n][rh * 2 + c];
                            int   ix = cb0 + n * 8 + c;
                            bool  gt = v > best[s];
                            sec[s] = fmaxf(sec[s], gt ? best[s] : v);
                            if (gt) { best[s] = v; bidx[s] = ix; }
                        }
                }
        }
        __syncthreads();
        if (i + 2 < 64) { load_chunk(sb + (i & 1) * CHUNK_B, i + 2, tid); CP_COMMIT(); }
    }

    // Reduce top-2 across the 4 lanes sharing each token row (lane&3 group)
#pragma unroll
    for (int s = 0; s < 4; s++) {
        float b_ = best[s], s_ = sec[s];
        int   i_ = bidx[s];
#pragma unroll
        for (int off = 1; off <= 2; off <<= 1) {
            float ob = __shfl_xor_sync(0xffffffffu, b_, off);
            float os = __shfl_xor_sync(0xffffffffu, s_, off);
            int   oi = __shfl_xor_sync(0xffffffffu, i_, off);
            bool take = (ob > b_) || (ob == b_ && oi < i_);
            s_ = fmaxf(fminf(b_, ob), fmaxf(s_, os));
            if (take) { b_ = ob; i_ = oi; }
        }
        best[s] = b_; sec[s] = s_; bidx[s] = i_;
    }

    // Merge the two n-warps via smem, then write idx (+ flag near-ties)
    float* rb = (float*)(smem + RED_OFF);
    float* rs = rb + 128;
    int*   ri = (int*)(rs + 128);
    __syncthreads();
    if (wn == 0 && (lane & 3) == 0) {
#pragma unroll
        for (int s = 0; s < 4; s++) {
            int tok = wm * 32 + (s >> 1) * 16 + (s & 1) * 8 + (lane >> 2);
            rb[tok] = best[s]; rs[tok] = sec[s]; ri[tok] = bidx[s];
        }
    }
    __syncthreads();
    if (wn == 1 && (lane & 3) == 0) {
#pragma unroll
        for (int s = 0; s < 4; s++) {
            int tok = wm * 32 + (s >> 1) * 16 + (s & 1) * 8 + (lane >> 2);
            float ob = rb[tok], os = rs[tok];
            int   oi = ri[tok];
            float b_ = best[s], s_ = sec[s];
            int   i_ = bidx[s];
            bool take = (ob > b_) || (ob == b_ && oi < i_);
            s_ = fmaxf(fminf(b_, ob), fmaxf(s_, os));
            if (take) { b_ = ob; i_ = oi; }
            g_idx[t0 + tok] = i_;
            if (b_ - s_ < EPS_MARGIN) {
                int p = atomicAdd(&g_nflag, 1);
                if (p < 8192) g_flist[p] = t0 + tok;
            }
        }
    }
}

// ---------------------------------------------------------------------------
// Kernel 3b: exact fp32 re-scan for near-tie tokens (expected ~10-30 tokens)
// ---------------------------------------------------------------------------
__global__ void fallback_kernel(const float* __restrict__ x,
                                const float* __restrict__ cb) {
    __shared__ float xs[64];
    __shared__ float wb[8];
    __shared__ int   wi[8];
    int n = g_nflag;
    if (n > 8192) n = 8192;
    for (int li = blockIdx.x; li < n; li += gridDim.x) {
        int token = g_flist[li];
        __syncthreads();
        if (threadIdx.x < 16)
            ((float4*)xs)[threadIdx.x] = ((const float4*)(x + token * 64))[threadIdx.x];
        __syncthreads();
        float best = -3.4e38f;
        int   bi = 0;
        for (int k = threadIdx.x; k < K_CODES; k += 256) {
            const float4* cr = (const float4*)(cb + k * 64);
            float s = 0.f;
#pragma unroll
            for (int q = 0; q < 16; q++) {
                float4 c4 = cr[q];
                s += xs[4 * q] * c4.x + xs[4 * q + 1] * c4.y
                   + xs[4 * q + 2] * c4.z + xs[4 * q + 3] * c4.w;
            }
            s -= g_halfnorm[k];
            if (s > best) { best = s; bi = k; }
        }
#pragma unroll
        for (int off = 16; off; off >>= 1) {
            float ob = __shfl_xor_sync(0xffffffffu, best, off);
            int   oi = __shfl_xor_sync(0xffffffffu, bi, off);
            if (ob > best || (ob == best && oi < bi)) { best = ob; bi = oi; }
        }
        if ((threadIdx.x & 31) == 0) { wb[threadIdx.x >> 5] = best; wi[threadIdx.x >> 5] = bi; }
        __syncthreads();
        if (threadIdx.x == 0) {
            float b = wb[0]; int ix = wi[0];
#pragma unroll
            for (int w = 1; w < 8; w++)
                if (wb[w] > b || (wb[w] == b && wi[w] < ix)) { b = wb[w]; ix = wi[w]; }
            g_idx[token] = ix;
        }
    }
}

// ---------------------------------------------------------------------------
// Kernel 4: one-hot fill (537 MB, HBM-write bound)
// ---------------------------------------------------------------------------
__global__ void discrete_kernel(float* __restrict__ out) {
    unsigned g = blockIdx.x * 256u + threadIdx.x;
    int n   = (int)(g >> 11);
    int c4  = (int)(g & 2047u);
    int idx = g_idx[n];
    float4 v = make_float4(0.f, 0.f, 0.f, 0.f);
    if ((idx >> 2) == c4) ((float*)&v)[idx & 3] = 1.0f;
    ((float4*)out)[g] = v;
}

// ---------------------------------------------------------------------------
// Kernel 5: quantized = codebook[idx[n]]
// ---------------------------------------------------------------------------
__global__ void quant_kernel(const float* __restrict__ cb, float* __restrict__ out) {
    int g = blockIdx.x * 256 + threadIdx.x;
    int n = g >> 4, d4 = g & 15;
    int idx = g_idx[n];
    ((float4*)out)[g] = ((const float4*)cb)[idx * 16 + d4];
}

// ---------------------------------------------------------------------------
// Kernel 6: histogram + scatter-add of x into accum
// ---------------------------------------------------------------------------
__global__ void scatter_kernel(const float* __restrict__ x) {
    int g = blockIdx.x * 256 + threadIdx.x;
    int n = g >> 6, d = g & 63;
    int idx = g_idx[n];
    atomicAdd(&g_accum[idx * DIM + d], x[g]);
    if (d == 0) atomicAdd(&g_hist[idx], 1.0f);
}

// ---------------------------------------------------------------------------
// Kernel 7: EMA update + normalization
// ---------------------------------------------------------------------------
__global__ void final_kernel(const float* __restrict__ ema_count,
                             const float* __restrict__ ema_weight,
                             float* __restrict__ out_count,
                             float* __restrict__ out_weight,
                             float* __restrict__ out_cb) {
    int g = blockIdx.x * 256 + threadIdx.x;
    int k = g >> 6, d = g & 63;
    const float DECAY = 0.99f, OMD = 1.0f - 0.99f, EPS = 1e-5f;
    float nc = ema_count[k] * DECAY + g_hist[k] * OMD;
    nc = (nc + EPS) / (32.0f + (float)K_CODES * EPS) * 32.0f;
    float nw = ema_weight[g] * DECAY + g_accum[g] * OMD;
    out_weight[g] = nw;
    out_cb[g]     = nw / nc;
    if (d == 0) out_count[k] = nc;
}

// ---------------------------------------------------------------------------
extern "C" void kernel_launch(void* const* d_in, const int* in_sizes, int n_in,
                              void* d_out, int out_size) {
    const float* x          = (const float*)d_in[0];
    const float* cb         = (const float*)d_in[1];
    const float* ema_count  = (const float*)d_in[2];
    const float* ema_weight = (const float*)d_in[3];
    float* out = (float*)d_out;

    cudaFuncSetAttribute(mma_argmax_kernel,
                         cudaFuncAttributeMaxDynamicSharedMemorySize, SM_TOTAL);

    prep_kernel     <<<32,   256>>>(cb);
    conv_x_kernel   <<<8192, 256>>>(x);
    conv_c_kernel   <<<4096, 256>>>(cb);
    mma_argmax_kernel<<<128, 256, SM_TOTAL>>>();
    fallback_kernel <<<64,   256>>>(x, cb);
    discrete_kernel <<<131072, 256>>>(out);
    quant_kernel    <<<1024, 256>>>(cb, out + OFF_QUANT);
    scatter_kernel  <<<4096, 256>>>(x);
    final_kernel    <<<2048, 256>>>(ema_count, ema_weight,
                                    out + OFF_COUNT, out + OFF_WEIGHT,
                                    out + OFF_CB);
}